// round 2
// baseline (speedup 1.0000x reference)
#include <cuda_runtime.h>
#include <math.h>

#define Nn 1024
#define Bb 8
#define Ff 128
#define Oo 128
#define Dd 3
#define Ll 2
#define TO 384  // 3*Oo

// ---------------- scratch (device globals: allocation-free) ----------------
__device__ float g_x[(size_t)Nn * Bb * Ff];                 // 4 MB
__device__ float g_support[(size_t)Dd * Bb * Nn * Oo];      // 12 MB
__device__ float g_agg[(size_t)Dd * Bb * Nn * Oo];          // 12 MB
__device__ float g_gi[(size_t)Dd * Bb * Nn * TO];           // 36 MB
__device__ float g_gh[(size_t)Nn * Bb * TO];                // 12 MB
__device__ float g_t[(size_t)Nn * Bb * Oo];                 // 4 MB
__device__ float g_WihT[Ll * Oo * TO];
__device__ float g_WhhT[Ll * Oo * TO];

// ---------------- transpose Wih/Whh: [L,3O,O] -> [L,O,3O] ------------------
__global__ void transpose_w(const float* __restrict__ Wih,
                            const float* __restrict__ Whh) {
    int idx = blockIdx.x * blockDim.x + threadIdx.x;  // over Ll*TO*Oo
    if (idx >= Ll * TO * Oo) return;
    int o = idx % Oo;
    int j = (idx / Oo) % TO;
    int l = idx / (Oo * TO);
    g_WihT[(l * Oo + o) * TO + j] = Wih[idx];
    g_WhhT[(l * Oo + o) * TO + j] = Whh[idx];
}

// ---------------- tiled fp32 GEMM ------------------------------------------
// C = A[M,K] * B[K,Ncols] (+bias) (+relu), batched over blockIdx.z.
// lda == K, ldb == Ncols (all operands plain row-major).
// OUT_MODE 0: C[z*strideC + row*Ncols + col]
// OUT_MODE 1 (support scatter): row encodes (n*Bb + b);
//            C[(((z*Bb + b)*Nn + n)*Oo) + col]
#define BM 64
#define BN 128
#define BK 16

template <int OUT_MODE, bool BIAS, bool RELU>
__launch_bounds__(256)
__global__ void gemm_k(const float* __restrict__ A, size_t strideA,
                       const float* __restrict__ Bm, size_t strideB,
                       const float* __restrict__ bias, int strideBias,
                       float* __restrict__ C, size_t strideC,
                       int M, int Ncols, int K) {
    __shared__ float As[BM][20];     // padded pitch (80B, float4-aligned)
    __shared__ float Bs[BK][BN];

    const int z = blockIdx.z;
    const float* Az = A + (size_t)z * strideA;
    const float* Bz = Bm + (size_t)z * strideB;

    const int tid = threadIdx.x;
    const int tx = tid & 15;
    const int ty = tid >> 4;
    const int m0 = blockIdx.y * BM;
    const int n0 = blockIdx.x * BN;
    const int row0 = ty * 4;
    const int cg = tx * 4;           // two col chunks: [cg..cg+3], [64+cg..64+cg+3]

    float acc[4][8];
#pragma unroll
    for (int i = 0; i < 4; i++)
#pragma unroll
        for (int j = 0; j < 8; j++) acc[i][j] = 0.f;

    const int aRow = tid >> 2;
    const int aC = (tid & 3) * 4;
    const int bRow0 = tid >> 5;
    const int bC = (tid & 31) * 4;

    const int ktiles = K / BK;
    for (int kt = 0; kt < ktiles; kt++) {
        const int k0 = kt * BK;
        // stage A tile (64x16), transposed-friendly padded layout
        float4 av = *(const float4*)(Az + (size_t)(m0 + aRow) * K + k0 + aC);
        *(float4*)&As[aRow][aC] = av;
        // stage B tile (16x128)
#pragma unroll
        for (int q = 0; q < 2; q++) {
            int r = bRow0 + q * 8;
            *(float4*)&Bs[r][bC] =
                *(const float4*)(Bz + (size_t)(k0 + r) * Ncols + n0 + bC);
        }
        __syncthreads();

#pragma unroll
        for (int kk = 0; kk < BK; kk++) {
            float a0 = As[row0 + 0][kk];
            float a1 = As[row0 + 1][kk];
            float a2 = As[row0 + 2][kk];
            float a3 = As[row0 + 3][kk];
            float4 b0 = *(const float4*)&Bs[kk][cg];
            float4 b1 = *(const float4*)&Bs[kk][64 + cg];
            float bv[8] = {b0.x, b0.y, b0.z, b0.w, b1.x, b1.y, b1.z, b1.w};
            float av4[4] = {a0, a1, a2, a3};
#pragma unroll
            for (int i = 0; i < 4; i++)
#pragma unroll
                for (int j = 0; j < 8; j++)
                    acc[i][j] = fmaf(av4[i], bv[j], acc[i][j]);
        }
        __syncthreads();
    }

    // epilogue
#pragma unroll
    for (int i = 0; i < 4; i++) {
        const int row = m0 + row0 + i;
#pragma unroll
        for (int jj = 0; jj < 8; jj++) {
            const int col = n0 + (jj < 4 ? cg + jj : 64 + cg + (jj - 4));
            float v = acc[i][jj];
            if (BIAS) v += bias[(size_t)strideBias * z + col];
            if (RELU) v = fmaxf(v, 0.f);
            size_t oidx;
            if (OUT_MODE == 0) {
                oidx = (size_t)z * strideC + (size_t)row * Ncols + col;
            } else {
                const int b = row & (Bb - 1);
                const int n = row >> 3;
                oidx = (((size_t)z * Bb + b) * Nn + n) * Oo + col;
            }
            C[oidx] = v;
        }
    }
}

// ---------------- fused GRU (sum over d) + relu + highway ------------------
__global__ void gru_highway(const float* __restrict__ x,
                            const float* __restrict__ gi,
                            const float* __restrict__ gh,
                            const float* __restrict__ t,
                            float* __restrict__ xout) {
    const int idx = blockIdx.x * blockDim.x + threadIdx.x;  // N*B*O
    const int o = idx & (Oo - 1);
    const int r = idx >> 7;          // n*Bb + b
    const int b = r & (Bb - 1);
    const int n = r >> 3;

    const float xv = x[idx];
    const float tv = t[idx];
    const size_t ghb = (size_t)r * TO;
    const float hr = gh[ghb + o];
    const float hz = gh[ghb + Oo + o];
    const float hn = gh[ghb + 2 * Oo + o];

    float sum = 0.f;
#pragma unroll
    for (int d = 0; d < Dd; d++) {
        const size_t gb = ((size_t)(d * Bb + b) * Nn + n) * TO;
        const float ir = gi[gb + o];
        const float iz = gi[gb + Oo + o];
        const float in_ = gi[gb + 2 * Oo + o];
        const float rg = 1.f / (1.f + expf(-(ir + hr)));
        const float zg = 1.f / (1.f + expf(-(iz + hz)));
        const float ng = tanhf(in_ + rg * hn);
        sum += (1.f - zg) * ng + zg * xv;
    }
    sum = fmaxf(sum, 0.f);
    xout[idx] = sum * tv + xv * (1.f - tv);
}

// ---------------- launch ---------------------------------------------------
extern "C" void kernel_launch(void* const* d_in, const int* in_sizes, int n_in,
                              void* d_out, int out_size) {
    const float* inputs = (const float*)d_in[0];
    const float* adj    = (const float*)d_in[1];
    const float* W      = (const float*)d_in[2];
    const float* Bc     = (const float*)d_in[3];
    const float* Wh     = (const float*)d_in[4];
    const float* Bh     = (const float*)d_in[5];
    const float* Wih    = (const float*)d_in[6];
    const float* Whh    = (const float*)d_in[7];
    const float* bih    = (const float*)d_in[8];
    const float* bhh    = (const float*)d_in[9];

    float *p_x, *p_sup, *p_agg, *p_gi, *p_gh, *p_t, *p_wiht, *p_whht;
    cudaGetSymbolAddress((void**)&p_x, g_x);
    cudaGetSymbolAddress((void**)&p_sup, g_support);
    cudaGetSymbolAddress((void**)&p_agg, g_agg);
    cudaGetSymbolAddress((void**)&p_gi, g_gi);
    cudaGetSymbolAddress((void**)&p_gh, g_gh);
    cudaGetSymbolAddress((void**)&p_t, g_t);
    cudaGetSymbolAddress((void**)&p_wiht, g_WihT);
    cudaGetSymbolAddress((void**)&p_whht, g_WhhT);

    transpose_w<<<(Ll * TO * Oo + 255) / 256, 256>>>(Wih, Whh);

    for (int l = 0; l < Ll; l++) {
        const float* xin = (l == 0) ? inputs : p_x;
        float* xout = (l == Ll - 1) ? (float*)d_out : p_x;

        // support[d,b,n,o] = x[n,b,:] @ W[l,d] + Bc[l,d]   (scatter OUT_MODE 1)
        gemm_k<1, true, false><<<dim3(1, (Nn * Bb) / BM, Dd), 256>>>(
            xin, 0, W + (size_t)l * Dd * Ff * Oo, (size_t)Ff * Oo,
            Bc + (size_t)l * Dd * Oo, Oo, p_sup, 0, Nn * Bb, Oo, Ff);

        // agg[d,b] = adj[d,b] @ support[d,b]   (24 batched 1024x128x1024 GEMMs)
        gemm_k<0, false, false><<<dim3(1, Nn / BM, Dd * Bb), 256>>>(
            adj, (size_t)Nn * Nn, p_sup, (size_t)Nn * Oo, nullptr, 0,
            p_agg, (size_t)Nn * Oo, Nn, Oo, Nn);

        // gi = agg @ WihT + bih   (24576 x 384 x 128)
        gemm_k<0, true, false><<<dim3(TO / BN, (Dd * Bb * Nn) / BM, 1), 256>>>(
            p_agg, 0, p_wiht + (size_t)l * Oo * TO, 0, bih + (size_t)l * TO, 0,
            p_gi, 0, Dd * Bb * Nn, TO, Oo);

        // gh = x @ WhhT + bhh   (computed ONCE, shared across d)
        gemm_k<0, true, false><<<dim3(TO / BN, (Nn * Bb) / BM, 1), 256>>>(
            xin, 0, p_whht + (size_t)l * Oo * TO, 0, bhh + (size_t)l * TO, 0,
            p_gh, 0, Nn * Bb, TO, Oo);

        // t = relu(x @ Wh + Bh)
        gemm_k<0, true, true><<<dim3(1, (Nn * Bb) / BM, 1), 256>>>(
            xin, 0, Wh + (size_t)l * Ff * Oo, 0, Bh + (size_t)l * Oo, 0,
            p_t, 0, Nn * Bb, Oo, Ff);

        // fused GRU + sum_d + relu + highway
        gru_highway<<<(Nn * Bb * Oo) / 256, 256>>>(xin, p_gi, p_gh, p_t, xout);
    }
}

// round 8
// speedup vs baseline: 1.2478x; 1.2478x over previous
#include <cuda_runtime.h>
#include <cuda_bf16.h>
#include <math.h>
#include <stdint.h>

#define Nn 1024
#define Bb 8
#define Ff 128
#define Oo 128
#define Dd 3
#define Ll 2
#define TO 384  // 3*Oo
#define DB (Dd * Bb)

// ---------------- scratch (device globals: allocation-free) ----------------
__device__ float g_x[(size_t)Nn * Bb * Ff];
__device__ float g_support[(size_t)DB * Nn * Oo];
__device__ float g_agg[(size_t)DB * Nn * Oo];
__device__ float g_gi[(size_t)DB * Nn * TO];
__device__ float g_gh[(size_t)Nn * Bb * TO];
__device__ float g_t[(size_t)Nn * Bb * Oo];
__device__ float g_WihT[Ll * Oo * TO];
__device__ float g_WhhT[Ll * Oo * TO];
__device__ __align__(256) __nv_bfloat16 g_adjh[(size_t)DB * Nn * Nn];
__device__ __align__(256) __nv_bfloat16 g_adjl[(size_t)DB * Nn * Nn];
__device__ __align__(256) __nv_bfloat16 g_supTh[(size_t)DB * Oo * Nn];
__device__ __align__(256) __nv_bfloat16 g_supTl[(size_t)DB * Oo * Nn];

__device__ __forceinline__ uint32_t smem_u32(const void* p) {
    uint32_t a;
    asm("{ .reg .u64 t; cvta.to.shared.u64 t, %1; cvt.u32.u64 %0, t; }"
        : "=r"(a) : "l"(p));
    return a;
}

#define LDMX4(r, addr)                                                        \
    asm volatile("ldmatrix.sync.aligned.m8n8.x4.shared.b16 {%0,%1,%2,%3}, [%4];" \
                 : "=r"((r)[0]), "=r"((r)[1]), "=r"((r)[2]), "=r"((r)[3])     \
                 : "r"(addr))

#define MMA16816(c, a, b)                                                     \
    asm volatile(                                                             \
        "mma.sync.aligned.m16n8k16.row.col.f32.bf16.bf16.f32 "                \
        "{%0,%1,%2,%3}, {%4,%5,%6,%7}, {%8,%9}, {%0,%1,%2,%3};"               \
        : "+f"((c)[0]), "+f"((c)[1]), "+f"((c)[2]), "+f"((c)[3])              \
        : "r"((a)[0]), "r"((a)[1]), "r"((a)[2]), "r"((a)[3]),                 \
          "r"((b)[0]), "r"((b)[1]))

// ---------------- transpose Wih/Whh: [L,3O,O] -> [L,O,3O] ------------------
__global__ void transpose_w(const float* __restrict__ Wih,
                            const float* __restrict__ Whh) {
    int idx = blockIdx.x * blockDim.x + threadIdx.x;
    if (idx >= Ll * TO * Oo) return;
    int o = idx % Oo;
    int j = (idx / Oo) % TO;
    int l = idx / (Oo * TO);
    g_WihT[(l * Oo + o) * TO + j] = Wih[idx];
    g_WhhT[(l * Oo + o) * TO + j] = Whh[idx];
}

// ---------------- adj fp32 -> bf16 hi/lo split (once per call) --------------
__global__ void adj_split(const float4* __restrict__ adj) {
    size_t i = (size_t)blockIdx.x * blockDim.x + threadIdx.x;
    if (i >= (size_t)DB * Nn * Nn / 4) return;
    float4 a = adj[i];
    __nv_bfloat162 h01 = __floats2bfloat162_rn(a.x, a.y);
    __nv_bfloat162 h23 = __floats2bfloat162_rn(a.z, a.w);
    __nv_bfloat162 l01 = __floats2bfloat162_rn(a.x - __low2float(h01),
                                               a.y - __high2float(h01));
    __nv_bfloat162 l23 = __floats2bfloat162_rn(a.z - __low2float(h23),
                                               a.w - __high2float(h23));
    ((__nv_bfloat162*)g_adjh)[i * 2 + 0] = h01;
    ((__nv_bfloat162*)g_adjh)[i * 2 + 1] = h23;
    ((__nv_bfloat162*)g_adjl)[i * 2 + 0] = l01;
    ((__nv_bfloat162*)g_adjl)[i * 2 + 1] = l23;
}

// ------- support [db][n][o] fp32 -> transposed bf16 hi/lo [db][o][n] -------
__global__ void sup_splitT(const float* __restrict__ sup) {
    __shared__ float tile[32][33];
    const int db = blockIdx.z, n0 = blockIdx.x * 32, o0 = blockIdx.y * 32;
    const int tx = threadIdx.x, ty = threadIdx.y;
    const float* s = sup + (size_t)db * Nn * Oo;
#pragma unroll
    for (int r = 0; r < 4; r++)
        tile[ty + r * 8][tx] = s[(size_t)(n0 + ty + r * 8) * Oo + o0 + tx];
    __syncthreads();
    const size_t ob = (size_t)db * Oo * Nn;
#pragma unroll
    for (int r = 0; r < 4; r++) {
        int o = o0 + ty + r * 8;
        float v = tile[tx][ty + r * 8];
        __nv_bfloat16 h = __float2bfloat16(v);
        __nv_bfloat16 l = __float2bfloat16(v - __bfloat162float(h));
        g_supTh[ob + (size_t)o * Nn + n0 + tx] = h;
        g_supTl[ob + (size_t)o * Nn + n0 + tx] = l;
    }
}

// ---------------- HMMA agg: agg[db] = adj[db] @ support[db] ----------------
// Split-bf16: D += Ah*Bh + Ah*Bl + Al*Bh (fp32 accum via mma.sync m16n8k16).
// CTA tile 128x128, K chunks of 64. 8 warps: warp_m = wid&3 (32 rows),
// warp_n = wid>>2 (64 cols). smem tiles 128 rows x 64 bf16, pitch 72 bf16
// (144 B: 16B-aligned, conflict-free for both staging and ldmatrix).
#define PITCH 72
#define TILE_B (128 * PITCH * 2)  // 18432 bytes per tile
#define AGG_SMEM (4 * TILE_B)     // 73728

__global__ __launch_bounds__(256, 1)
void agg_hmma_kernel(const __nv_bfloat16* __restrict__ adjh,
                     const __nv_bfloat16* __restrict__ adjl,
                     float* __restrict__ agg) {
    extern __shared__ __nv_bfloat16 smem[];
    const uint32_t sbase = smem_u32(smem);
    const uint32_t sAh = sbase;
    const uint32_t sAl = sbase + TILE_B;
    const uint32_t sBh = sbase + 2 * TILE_B;
    const uint32_t sBl = sbase + 3 * TILE_B;

    const int tid = threadIdx.x, wid = tid >> 5, lane = tid & 31;
    const int mtile = blockIdx.x, db = blockIdx.y;
    const int wm0 = (wid & 3) * 32;   // warp M offset within CTA tile
    const int wn0 = (wid >> 2) * 64;  // warp N offset

    const __nv_bfloat16* Ah = adjh + ((size_t)db * Nn + mtile * 128) * Nn;
    const __nv_bfloat16* Al = adjl + ((size_t)db * Nn + mtile * 128) * Nn;
    const __nv_bfloat16* Bh = g_supTh + (size_t)db * Oo * Nn;
    const __nv_bfloat16* Bl = g_supTl + (size_t)db * Oo * Nn;

    float acc[2][8][4];
#pragma unroll
    for (int i = 0; i < 2; i++)
#pragma unroll
        for (int j = 0; j < 8; j++)
#pragma unroll
            for (int q = 0; q < 4; q++) acc[i][j][q] = 0.f;

    // ldmatrix source addresses (row = lane&15, col-group = lane>>4)
    const uint32_t lrow = lane & 15;
    const uint32_t lcg = (lane >> 4) * 16;  // byte offset of 8-col group

    for (int c = 0; c < 16; c++) {
        const int koff = c * 64;
        // stage 4 tiles: 128 rows x 64 bf16 each, 1024 uint4 per tile
#pragma unroll
        for (int k = 0; k < 4; k++) {
            const int u = tid + k * 256;
            const int row = u >> 3, grp = u & 7;
            const uint32_t so = row * (PITCH * 2) + grp * 16;
            const size_t go = (size_t)row * Nn + koff + grp * 8;
            *(uint4*)((char*)smem + (sAh - sbase) + so) = *(const uint4*)(Ah + go);
            *(uint4*)((char*)smem + (sAl - sbase) + so) = *(const uint4*)(Al + go);
            *(uint4*)((char*)smem + (sBh - sbase) + so) = *(const uint4*)(Bh + go);
            *(uint4*)((char*)smem + (sBl - sbase) + so) = *(const uint4*)(Bl + go);
        }
        __syncthreads();

#pragma unroll
        for (int ks = 0; ks < 4; ks++) {
            const uint32_t kb = ks * 32 + lcg;  // byte offset within 64-col chunk
            uint32_t a_h[2][4], a_l[2][4];
#pragma unroll
            for (int i = 0; i < 2; i++) {
                const uint32_t ro = (wm0 + i * 16 + lrow) * (PITCH * 2) + kb;
                LDMX4(a_h[i], sAh + ro);
                LDMX4(a_l[i], sAl + ro);
            }
            uint32_t b_h[8][2], b_l[8][2];
#pragma unroll
            for (int j2 = 0; j2 < 4; j2++) {
                const uint32_t ro = (wn0 + j2 * 16 + lrow) * (PITCH * 2) + kb;
                uint32_t rh[4], rl[4];
                LDMX4(rh, sBh + ro);
                LDMX4(rl, sBl + ro);
                b_h[2 * j2][0] = rh[0]; b_h[2 * j2][1] = rh[2];
                b_h[2 * j2 + 1][0] = rh[1]; b_h[2 * j2 + 1][1] = rh[3];
                b_l[2 * j2][0] = rl[0]; b_l[2 * j2][1] = rl[2];
                b_l[2 * j2 + 1][0] = rl[1]; b_l[2 * j2 + 1][1] = rl[3];
            }
#pragma unroll
            for (int i = 0; i < 2; i++)
#pragma unroll
                for (int j = 0; j < 8; j++) {
                    MMA16816(acc[i][j], a_h[i], b_h[j]);
                    MMA16816(acc[i][j], a_h[i], b_l[j]);
                    MMA16816(acc[i][j], a_l[i], b_h[j]);
                }
        }
        __syncthreads();
    }

    // epilogue: direct float2 stores
    float* dst = agg + ((size_t)db * Nn + mtile * 128) * Oo;
    const int g = lane >> 2, t2 = (lane & 3) * 2;
#pragma unroll
    for (int i = 0; i < 2; i++) {
        const int r0 = wm0 + i * 16 + g;
#pragma unroll
        for (int j = 0; j < 8; j++) {
            const int col = wn0 + j * 8 + t2;
            *(float2*)(dst + (size_t)r0 * Oo + col) =
                make_float2(acc[i][j][0], acc[i][j][1]);
            *(float2*)(dst + (size_t)(r0 + 8) * Oo + col) =
                make_float2(acc[i][j][2], acc[i][j][3]);
        }
    }
}

// ---------------- tiled fp32 GEMM (unchanged) ------------------------------
#define BM 64
#define BN 128
#define BK 16

template <int OUT_MODE, bool BIAS, bool RELU>
__launch_bounds__(256)
__global__ void gemm_k(const float* __restrict__ A, size_t strideA,
                       const float* __restrict__ Bm, size_t strideB,
                       const float* __restrict__ bias, int strideBias,
                       float* __restrict__ C, size_t strideC,
                       int M, int Ncols, int K) {
    __shared__ float As[BM][20];
    __shared__ float Bs[BK][BN];

    const int z = blockIdx.z;
    const float* Az = A + (size_t)z * strideA;
    const float* Bz = Bm + (size_t)z * strideB;

    const int tid = threadIdx.x;
    const int tx = tid & 15;
    const int ty = tid >> 4;
    const int m0 = blockIdx.y * BM;
    const int n0 = blockIdx.x * BN;
    const int row0 = ty * 4;
    const int cg = tx * 4;

    float acc[4][8];
#pragma unroll
    for (int i = 0; i < 4; i++)
#pragma unroll
        for (int j = 0; j < 8; j++) acc[i][j] = 0.f;

    const int aRow = tid >> 2;
    const int aC = (tid & 3) * 4;
    const int bRow0 = tid >> 5;
    const int bC = (tid & 31) * 4;

    const int ktiles = K / BK;
    for (int kt = 0; kt < ktiles; kt++) {
        const int k0 = kt * BK;
        float4 av = *(const float4*)(Az + (size_t)(m0 + aRow) * K + k0 + aC);
        *(float4*)&As[aRow][aC] = av;
#pragma unroll
        for (int q = 0; q < 2; q++) {
            int r = bRow0 + q * 8;
            *(float4*)&Bs[r][bC] =
                *(const float4*)(Bz + (size_t)(k0 + r) * Ncols + n0 + bC);
        }
        __syncthreads();

#pragma unroll
        for (int kk = 0; kk < BK; kk++) {
            float a0 = As[row0 + 0][kk];
            float a1 = As[row0 + 1][kk];
            float a2 = As[row0 + 2][kk];
            float a3 = As[row0 + 3][kk];
            float4 b0 = *(const float4*)&Bs[kk][cg];
            float4 b1 = *(const float4*)&Bs[kk][64 + cg];
            float bv[8] = {b0.x, b0.y, b0.z, b0.w, b1.x, b1.y, b1.z, b1.w};
            float av4[4] = {a0, a1, a2, a3};
#pragma unroll
            for (int i = 0; i < 4; i++)
#pragma unroll
                for (int j = 0; j < 8; j++)
                    acc[i][j] = fmaf(av4[i], bv[j], acc[i][j]);
        }
        __syncthreads();
    }

#pragma unroll
    for (int i = 0; i < 4; i++) {
        const int row = m0 + row0 + i;
#pragma unroll
        for (int jj = 0; jj < 8; jj++) {
            const int col = n0 + (jj < 4 ? cg + jj : 64 + cg + (jj - 4));
            float v = acc[i][jj];
            if (BIAS) v += bias[(size_t)strideBias * z + col];
            if (RELU) v = fmaxf(v, 0.f);
            size_t oidx;
            if (OUT_MODE == 0) {
                oidx = (size_t)z * strideC + (size_t)row * Ncols + col;
            } else {
                const int b = row & (Bb - 1);
                const int n = row >> 3;
                oidx = (((size_t)z * Bb + b) * Nn + n) * Oo + col;
            }
            C[oidx] = v;
        }
    }
}

// ---------------- fused GRU (sum over d) + relu + highway ------------------
__global__ void gru_highway(const float* __restrict__ x,
                            const float* __restrict__ gi,
                            const float* __restrict__ gh,
                            const float* __restrict__ t,
                            float* __restrict__ xout) {
    const int idx = blockIdx.x * blockDim.x + threadIdx.x;
    const int o = idx & (Oo - 1);
    const int r = idx >> 7;
    const int b = r & (Bb - 1);
    const int n = r >> 3;

    const float xv = x[idx];
    const float tv = t[idx];
    const size_t ghb = (size_t)r * TO;
    const float hr = gh[ghb + o];
    const float hz = gh[ghb + Oo + o];
    const float hn = gh[ghb + 2 * Oo + o];

    float sum = 0.f;
#pragma unroll
    for (int d = 0; d < Dd; d++) {
        const size_t gb = ((size_t)(d * Bb + b) * Nn + n) * TO;
        const float ir = gi[gb + o];
        const float iz = gi[gb + Oo + o];
        const float in_ = gi[gb + 2 * Oo + o];
        const float rg = 1.f / (1.f + expf(-(ir + hr)));
        const float zg = 1.f / (1.f + expf(-(iz + hz)));
        const float ng = tanhf(in_ + rg * hn);
        sum += (1.f - zg) * ng + zg * xv;
    }
    sum = fmaxf(sum, 0.f);
    xout[idx] = sum * tv + xv * (1.f - tv);
}

// ---------------- launch ---------------------------------------------------
extern "C" void kernel_launch(void* const* d_in, const int* in_sizes, int n_in,
                              void* d_out, int out_size) {
    const float* inputs = (const float*)d_in[0];
    const float* adj    = (const float*)d_in[1];
    const float* W      = (const float*)d_in[2];
    const float* Bc     = (const float*)d_in[3];
    const float* Wh     = (const float*)d_in[4];
    const float* Bh     = (const float*)d_in[5];
    const float* Wih    = (const float*)d_in[6];
    const float* Whh    = (const float*)d_in[7];
    const float* bih    = (const float*)d_in[8];
    const float* bhh    = (const float*)d_in[9];

    float *p_x, *p_sup, *p_agg, *p_gi, *p_gh, *p_t, *p_wiht, *p_whht;
    __nv_bfloat16 *p_adjh, *p_adjl;
    cudaGetSymbolAddress((void**)&p_x, g_x);
    cudaGetSymbolAddress((void**)&p_sup, g_support);
    cudaGetSymbolAddress((void**)&p_agg, g_agg);
    cudaGetSymbolAddress((void**)&p_gi, g_gi);
    cudaGetSymbolAddress((void**)&p_gh, g_gh);
    cudaGetSymbolAddress((void**)&p_t, g_t);
    cudaGetSymbolAddress((void**)&p_wiht, g_WihT);
    cudaGetSymbolAddress((void**)&p_whht, g_WhhT);
    cudaGetSymbolAddress((void**)&p_adjh, g_adjh);
    cudaGetSymbolAddress((void**)&p_adjl, g_adjl);

    cudaFuncSetAttribute(agg_hmma_kernel,
                         cudaFuncAttributeMaxDynamicSharedMemorySize, AGG_SMEM);

    transpose_w<<<(Ll * TO * Oo + 255) / 256, 256>>>(Wih, Whh);
    adj_split<<<(int)(((size_t)DB * Nn * Nn / 4 + 255) / 256), 256>>>(
        (const float4*)adj);

    for (int l = 0; l < Ll; l++) {
        const float* xin = (l == 0) ? inputs : p_x;
        float* xout = (l == Ll - 1) ? (float*)d_out : p_x;

        // support[d,b,n,o] = x @ W[l,d] + Bc[l,d]
        gemm_k<1, true, false><<<dim3(1, (Nn * Bb) / BM, Dd), 256>>>(
            xin, 0, W + (size_t)l * Dd * Ff * Oo, (size_t)Ff * Oo,
            Bc + (size_t)l * Dd * Oo, Oo, p_sup, 0, Nn * Bb, Oo, Ff);

        // supT hi/lo bf16 [db][o][n]
        sup_splitT<<<dim3(Nn / 32, Oo / 32, DB), dim3(32, 8)>>>(p_sup);

        // agg[db] = adj[db] @ support[db]  — HMMA split-bf16
        agg_hmma_kernel<<<dim3(Nn / 128, DB), 256, AGG_SMEM>>>(
            p_adjh, p_adjl, p_agg);

        // gi = agg @ WihT + bih
        gemm_k<0, true, false><<<dim3(TO / BN, (DB * Nn) / BM, 1), 256>>>(
            p_agg, 0, p_wiht + (size_t)l * Oo * TO, 0, bih + (size_t)l * TO, 0,
            p_gi, 0, DB * Nn, TO, Oo);

        // gh = x @ WhhT + bhh (once, shared across d)
        gemm_k<0, true, false><<<dim3(TO / BN, (Nn * Bb) / BM, 1), 256>>>(
            xin, 0, p_whht + (size_t)l * Oo * TO, 0, bhh + (size_t)l * TO, 0,
            p_gh, 0, Nn * Bb, TO, Oo);

        // t = relu(x @ Wh + Bh)
        gemm_k<0, true, true><<<dim3(1, (Nn * Bb) / BM, 1), 256>>>(
            xin, 0, Wh + (size_t)l * Ff * Oo, 0, Bh + (size_t)l * Oo, 0,
            p_t, 0, Nn * Bb, Oo, Ff);

        gru_highway<<<(Nn * Bb * Oo) / 256, 256>>>(xin, p_gi, p_gh, p_t, xout);
    }
}

// round 9
// speedup vs baseline: 1.5693x; 1.2576x over previous
#include <cuda_runtime.h>
#include <cuda_bf16.h>
#include <math.h>
#include <stdint.h>

#define Nn 1024
#define Bb 8
#define Ff 128
#define Oo 128
#define Dd 3
#define Ll 2
#define TO 384  // 3*Oo
#define DB (Dd * Bb)

typedef __nv_bfloat16 bf16;

// ---------------- scratch (device globals: allocation-free) ----------------
__device__ float g_x[(size_t)Nn * Bb * Ff];
__device__ float g_support[(size_t)DB * Nn * Oo];
__device__ float g_gi[(size_t)DB * Nn * TO];
__device__ float g_gh[(size_t)Nn * Bb * TO];
__device__ float g_t[(size_t)Nn * Bb * Oo];
__device__ __align__(256) bf16 g_adjh[(size_t)DB * Nn * Nn];
__device__ __align__(256) bf16 g_adjl[(size_t)DB * Nn * Nn];
__device__ __align__(256) bf16 g_supTh[(size_t)DB * Oo * Nn];
__device__ __align__(256) bf16 g_supTl[(size_t)DB * Oo * Nn];
__device__ __align__(256) bf16 g_aggh[(size_t)DB * Nn * Oo];
__device__ __align__(256) bf16 g_aggl[(size_t)DB * Nn * Oo];
__device__ __align__(256) bf16 g_xh[(size_t)Nn * Bb * Ff];
__device__ __align__(256) bf16 g_xl[(size_t)Nn * Bb * Ff];
__device__ __align__(256) bf16 g_Wih_h[Ll * TO * Oo], g_Wih_l[Ll * TO * Oo];
__device__ __align__(256) bf16 g_Whh_h[Ll * TO * Oo], g_Whh_l[Ll * TO * Oo];
__device__ __align__(256) bf16 g_WT_h[Ll * Dd * Oo * Ff], g_WT_l[Ll * Dd * Oo * Ff];
__device__ __align__(256) bf16 g_WhT_h[Ll * Oo * Ff], g_WhT_l[Ll * Oo * Ff];

__device__ __forceinline__ uint32_t smem_u32(const void* p) {
    uint32_t a;
    asm("{ .reg .u64 t; cvta.to.shared.u64 t, %1; cvt.u32.u64 %0, t; }"
        : "=r"(a) : "l"(p));
    return a;
}

#define LDMX4(r, addr)                                                        \
    asm volatile("ldmatrix.sync.aligned.m8n8.x4.shared.b16 {%0,%1,%2,%3}, [%4];" \
                 : "=r"((r)[0]), "=r"((r)[1]), "=r"((r)[2]), "=r"((r)[3])     \
                 : "r"(addr))

#define MMA16816(c, a, b)                                                     \
    asm volatile(                                                             \
        "mma.sync.aligned.m16n8k16.row.col.f32.bf16.bf16.f32 "                \
        "{%0,%1,%2,%3}, {%4,%5,%6,%7}, {%8,%9}, {%0,%1,%2,%3};"               \
        : "+f"((c)[0]), "+f"((c)[1]), "+f"((c)[2]), "+f"((c)[3])              \
        : "r"((a)[0]), "r"((a)[1]), "r"((a)[2]), "r"((a)[3]),                 \
          "r"((b)[0]), "r"((b)[1]))

__device__ __forceinline__ void split2(float v, bf16& h, bf16& l) {
    h = __float2bfloat16(v);
    l = __float2bfloat16(v - __bfloat162float(h));
}

// ---------------- prep kernels ---------------------------------------------
__global__ void split_elem(const float* __restrict__ src, bf16* __restrict__ h,
                           bf16* __restrict__ l, int count) {
    int i = blockIdx.x * blockDim.x + threadIdx.x;
    if (i >= count) return;
    split2(src[i], h[i], l[i]);
}

// batched 128x128 transpose + split: src [z][R=128][C=128] -> dst [z][C][R]
__global__ void transpose_split(const float* __restrict__ src,
                                bf16* __restrict__ dh, bf16* __restrict__ dl) {
    __shared__ float tile[32][33];
    const int z = blockIdx.z, r0 = blockIdx.x * 32, c0 = blockIdx.y * 32;
    const int tx = threadIdx.x, ty = threadIdx.y;
    const float* s = src + (size_t)z * 128 * 128;
#pragma unroll
    for (int r = 0; r < 4; r++)
        tile[ty + r * 8][tx] = s[(size_t)(r0 + ty + r * 8) * 128 + c0 + tx];
    __syncthreads();
    const size_t ob = (size_t)z * 128 * 128;
#pragma unroll
    for (int r = 0; r < 4; r++) {
        int c = c0 + ty + r * 8;
        bf16 h, l;
        split2(tile[tx][ty + r * 8], h, l);
        dh[ob + (size_t)c * 128 + r0 + tx] = h;
        dl[ob + (size_t)c * 128 + r0 + tx] = l;
    }
}

// ---------------- adj fp32 -> bf16 hi/lo split (once per call) --------------
__global__ void adj_split(const float4* __restrict__ adj) {
    size_t i = (size_t)blockIdx.x * blockDim.x + threadIdx.x;
    if (i >= (size_t)DB * Nn * Nn / 4) return;
    float4 a = adj[i];
    __nv_bfloat162 h01 = __floats2bfloat162_rn(a.x, a.y);
    __nv_bfloat162 h23 = __floats2bfloat162_rn(a.z, a.w);
    __nv_bfloat162 l01 = __floats2bfloat162_rn(a.x - __low2float(h01),
                                               a.y - __high2float(h01));
    __nv_bfloat162 l23 = __floats2bfloat162_rn(a.z - __low2float(h23),
                                               a.w - __high2float(h23));
    ((__nv_bfloat162*)g_adjh)[i * 2 + 0] = h01;
    ((__nv_bfloat162*)g_adjh)[i * 2 + 1] = h23;
    ((__nv_bfloat162*)g_adjl)[i * 2 + 0] = l01;
    ((__nv_bfloat162*)g_adjl)[i * 2 + 1] = l23;
}

// ------- support [db][n][o] fp32 -> transposed bf16 hi/lo [db][o][n] -------
__global__ void sup_splitT(const float* __restrict__ sup) {
    __shared__ float tile[32][33];
    const int db = blockIdx.z, n0 = blockIdx.x * 32, o0 = blockIdx.y * 32;
    const int tx = threadIdx.x, ty = threadIdx.y;
    const float* s = sup + (size_t)db * Nn * Oo;
#pragma unroll
    for (int r = 0; r < 4; r++)
        tile[ty + r * 8][tx] = s[(size_t)(n0 + ty + r * 8) * Oo + o0 + tx];
    __syncthreads();
    const size_t ob = (size_t)db * Oo * Nn;
#pragma unroll
    for (int r = 0; r < 4; r++) {
        int o = o0 + ty + r * 8;
        bf16 h, l;
        split2(tile[tx][ty + r * 8], h, l);
        g_supTh[ob + (size_t)o * Nn + n0 + tx] = h;
        g_supTl[ob + (size_t)o * Nn + n0 + tx] = l;
    }
}

// ================= unified split-bf16 HMMA GEMM ============================
// C[M,N] = A[M,K] @ B[N,K]^T  (both operands pre-split bf16 hi/lo, K-major)
// D += Ah*Bh + Ah*Bl + Al*Bh  (fp32 accumulate; ~fp32 precision)
// CTA tile 128x128, K staged in chunks of 64. 8 warps (4 M x 2 N), 32x64 each.
// OUT_MODE 0: fp32 C[z*strideCz + row*Ncols + col]
// OUT_MODE 1: fp32 scatter (support): row=(n*8+b) -> [((z*8+b)*1024+n)*128+col]
// OUT_MODE 2: bf16 hi/lo split out (Ch/Cl), Ncols=128
#define PITCH 72
#define TILE_B (128 * PITCH * 2)  // 18432 bytes per tile
#define HG_SMEM (4 * TILE_B)      // 73728

template <int OUT_MODE, bool BIAS, bool RELU>
__global__ __launch_bounds__(256, 1)
void hmma_gemm(const bf16* __restrict__ Ah_, const bf16* __restrict__ Al_,
               size_t strideAz,
               const bf16* __restrict__ Bh_, const bf16* __restrict__ Bl_,
               size_t strideBz,
               const float* __restrict__ bias, int biasStrideZ,
               float* __restrict__ C, size_t strideCz,
               bf16* __restrict__ Ch, bf16* __restrict__ Cl,
               int Ncols, int K) {
    extern __shared__ bf16 smem[];
    const uint32_t sbase = smem_u32(smem);
    const uint32_t sAh = sbase;
    const uint32_t sAl = sbase + TILE_B;
    const uint32_t sBh = sbase + 2 * TILE_B;
    const uint32_t sBl = sbase + 3 * TILE_B;

    const int tid = threadIdx.x, wid = tid >> 5, lane = tid & 31;
    const int n0 = blockIdx.x * 128, m0 = blockIdx.y * 128, z = blockIdx.z;
    const int wm0 = (wid & 3) * 32;
    const int wn0 = (wid >> 2) * 64;

    const bf16* Ah = Ah_ + (size_t)z * strideAz + (size_t)m0 * K;
    const bf16* Al = Al_ + (size_t)z * strideAz + (size_t)m0 * K;
    const bf16* Bh = Bh_ + (size_t)z * strideBz + (size_t)n0 * K;
    const bf16* Bl = Bl_ + (size_t)z * strideBz + (size_t)n0 * K;

    float acc[2][8][4];
#pragma unroll
    for (int i = 0; i < 2; i++)
#pragma unroll
        for (int j = 0; j < 8; j++)
#pragma unroll
            for (int q = 0; q < 4; q++) acc[i][j][q] = 0.f;

    const uint32_t lrow = lane & 15;
    const uint32_t lcg = (lane >> 4) * 16;

    const int chunks = K >> 6;
    for (int c = 0; c < chunks; c++) {
        const int koff = c * 64;
#pragma unroll
        for (int k = 0; k < 4; k++) {
            const int u = tid + k * 256;
            const int row = u >> 3, grp = u & 7;
            const uint32_t so = row * (PITCH * 2) + grp * 16;
            const size_t go = (size_t)row * K + koff + grp * 8;
            *(uint4*)((char*)smem + (sAh - sbase) + so) = *(const uint4*)(Ah + go);
            *(uint4*)((char*)smem + (sAl - sbase) + so) = *(const uint4*)(Al + go);
            *(uint4*)((char*)smem + (sBh - sbase) + so) = *(const uint4*)(Bh + go);
            *(uint4*)((char*)smem + (sBl - sbase) + so) = *(const uint4*)(Bl + go);
        }
        __syncthreads();

#pragma unroll
        for (int ks = 0; ks < 4; ks++) {
            const uint32_t kb = ks * 32 + lcg;
            uint32_t a_h[2][4], a_l[2][4];
#pragma unroll
            for (int i = 0; i < 2; i++) {
                const uint32_t ro = (wm0 + i * 16 + lrow) * (PITCH * 2) + kb;
                LDMX4(a_h[i], sAh + ro);
                LDMX4(a_l[i], sAl + ro);
            }
            uint32_t b_h[8][2], b_l[8][2];
#pragma unroll
            for (int j2 = 0; j2 < 4; j2++) {
                const uint32_t ro = (wn0 + j2 * 16 + lrow) * (PITCH * 2) + kb;
                uint32_t rh[4], rl[4];
                LDMX4(rh, sBh + ro);
                LDMX4(rl, sBl + ro);
                b_h[2 * j2][0] = rh[0]; b_h[2 * j2][1] = rh[2];
                b_h[2 * j2 + 1][0] = rh[1]; b_h[2 * j2 + 1][1] = rh[3];
                b_l[2 * j2][0] = rl[0]; b_l[2 * j2][1] = rl[2];
                b_l[2 * j2 + 1][0] = rl[1]; b_l[2 * j2 + 1][1] = rl[3];
            }
#pragma unroll
            for (int i = 0; i < 2; i++)
#pragma unroll
                for (int j = 0; j < 8; j++) {
                    MMA16816(acc[i][j], a_h[i], b_h[j]);
                    MMA16816(acc[i][j], a_h[i], b_l[j]);
                    MMA16816(acc[i][j], a_l[i], b_h[j]);
                }
        }
        __syncthreads();
    }

    // ----- epilogue -----
    const int g = lane >> 2, t2 = (lane & 3) * 2;
#pragma unroll
    for (int i = 0; i < 2; i++) {
#pragma unroll
        for (int half = 0; half < 2; half++) {
            const int rloc = wm0 + i * 16 + half * 8 + g;  // 0..127
#pragma unroll
            for (int j = 0; j < 8; j++) {
                const int col = n0 + wn0 + j * 8 + t2;
                float v0 = acc[i][j][half * 2 + 0];
                float v1 = acc[i][j][half * 2 + 1];
                if (BIAS) {
                    const float* bz = bias + (size_t)biasStrideZ * z;
                    v0 += bz[col];
                    v1 += bz[col + 1];
                }
                if (RELU) { v0 = fmaxf(v0, 0.f); v1 = fmaxf(v1, 0.f); }
                if (OUT_MODE == 0) {
                    const size_t o = (size_t)z * strideCz +
                                     (size_t)(m0 + rloc) * Ncols + col;
                    *(float2*)(C + o) = make_float2(v0, v1);
                } else if (OUT_MODE == 1) {
                    const int row = m0 + rloc;
                    const int b = row & 7, n = row >> 3;
                    const size_t o = (((size_t)z * Bb + b) * Nn + n) * Oo + col;
                    *(float2*)(C + o) = make_float2(v0, v1);
                } else {
                    bf16 h0, l0, h1, l1;
                    split2(v0, h0, l0);
                    split2(v1, h1, l1);
                    const size_t o = (size_t)z * strideCz +
                                     (size_t)(m0 + rloc) * 128 + col;
                    *(__nv_bfloat162*)(Ch + o) = __nv_bfloat162(h0, h1);
                    *(__nv_bfloat162*)(Cl + o) = __nv_bfloat162(l0, l1);
                }
            }
        }
    }
}

// ---------------- fused GRU (sum over d) + relu + highway ------------------
__global__ void gru_highway(const float* __restrict__ x,
                            const float* __restrict__ gi,
                            const float* __restrict__ gh,
                            const float* __restrict__ t,
                            float* __restrict__ xout,
                            bf16* __restrict__ xh, bf16* __restrict__ xl,
                            int writeSplit) {
    const int idx = blockIdx.x * blockDim.x + threadIdx.x;
    const int o = idx & (Oo - 1);
    const int r = idx >> 7;
    const int b = r & (Bb - 1);
    const int n = r >> 3;

    const float xv = x[idx];
    const float tv = t[idx];
    const size_t ghb = (size_t)r * TO;
    const float hr = gh[ghb + o];
    const float hz = gh[ghb + Oo + o];
    const float hn = gh[ghb + 2 * Oo + o];

    float sum = 0.f;
#pragma unroll
    for (int d = 0; d < Dd; d++) {
        const size_t gb = ((size_t)(d * Bb + b) * Nn + n) * TO;
        const float ir = gi[gb + o];
        const float iz = gi[gb + Oo + o];
        const float in_ = gi[gb + 2 * Oo + o];
        const float rg = 1.f / (1.f + expf(-(ir + hr)));
        const float zg = 1.f / (1.f + expf(-(iz + hz)));
        const float ng = tanhf(in_ + rg * hn);
        sum += (1.f - zg) * ng + zg * xv;
    }
    sum = fmaxf(sum, 0.f);
    const float out = sum * tv + xv * (1.f - tv);
    xout[idx] = out;
    if (writeSplit) {
        bf16 h, l;
        split2(out, h, l);
        xh[idx] = h;
        xl[idx] = l;
    }
}

// ---------------- launch ---------------------------------------------------
extern "C" void kernel_launch(void* const* d_in, const int* in_sizes, int n_in,
                              void* d_out, int out_size) {
    const float* inputs = (const float*)d_in[0];
    const float* adj    = (const float*)d_in[1];
    const float* W      = (const float*)d_in[2];
    const float* Bc     = (const float*)d_in[3];
    const float* Wh     = (const float*)d_in[4];
    const float* Bh     = (const float*)d_in[5];
    const float* Wih    = (const float*)d_in[6];
    const float* Whh    = (const float*)d_in[7];
    const float* bih    = (const float*)d_in[8];
    const float* bhh    = (const float*)d_in[9];

    float *p_x, *p_sup, *p_gi, *p_gh, *p_t;
    bf16 *p_adjh, *p_adjl, *p_supTh, *p_supTl, *p_aggh, *p_aggl, *p_xh, *p_xl;
    bf16 *p_Wih_h, *p_Wih_l, *p_Whh_h, *p_Whh_l, *p_WT_h, *p_WT_l, *p_WhT_h, *p_WhT_l;
    cudaGetSymbolAddress((void**)&p_x, g_x);
    cudaGetSymbolAddress((void**)&p_sup, g_support);
    cudaGetSymbolAddress((void**)&p_gi, g_gi);
    cudaGetSymbolAddress((void**)&p_gh, g_gh);
    cudaGetSymbolAddress((void**)&p_t, g_t);
    cudaGetSymbolAddress((void**)&p_adjh, g_adjh);
    cudaGetSymbolAddress((void**)&p_adjl, g_adjl);
    cudaGetSymbolAddress((void**)&p_supTh, g_supTh);
    cudaGetSymbolAddress((void**)&p_supTl, g_supTl);
    cudaGetSymbolAddress((void**)&p_aggh, g_aggh);
    cudaGetSymbolAddress((void**)&p_aggl, g_aggl);
    cudaGetSymbolAddress((void**)&p_xh, g_xh);
    cudaGetSymbolAddress((void**)&p_xl, g_xl);
    cudaGetSymbolAddress((void**)&p_Wih_h, g_Wih_h);
    cudaGetSymbolAddress((void**)&p_Wih_l, g_Wih_l);
    cudaGetSymbolAddress((void**)&p_Whh_h, g_Whh_h);
    cudaGetSymbolAddress((void**)&p_Whh_l, g_Whh_l);
    cudaGetSymbolAddress((void**)&p_WT_h, g_WT_h);
    cudaGetSymbolAddress((void**)&p_WT_l, g_WT_l);
    cudaGetSymbolAddress((void**)&p_WhT_h, g_WhT_h);
    cudaGetSymbolAddress((void**)&p_WhT_l, g_WhT_l);

    cudaFuncSetAttribute(hmma_gemm<0, true, false>,
                         cudaFuncAttributeMaxDynamicSharedMemorySize, HG_SMEM);
    cudaFuncSetAttribute(hmma_gemm<0, true, true>,
                         cudaFuncAttributeMaxDynamicSharedMemorySize, HG_SMEM);
    cudaFuncSetAttribute(hmma_gemm<1, true, false>,
                         cudaFuncAttributeMaxDynamicSharedMemorySize, HG_SMEM);
    cudaFuncSetAttribute(hmma_gemm<2, false, false>,
                         cudaFuncAttributeMaxDynamicSharedMemorySize, HG_SMEM);

    // ---- one-time prep ----
    adj_split<<<(int)(((size_t)DB * Nn * Nn / 4 + 255) / 256), 256>>>(
        (const float4*)adj);
    split_elem<<<(Ll * TO * Oo + 255) / 256, 256>>>(Wih, p_Wih_h, p_Wih_l,
                                                    Ll * TO * Oo);
    split_elem<<<(Ll * TO * Oo + 255) / 256, 256>>>(Whh, p_Whh_h, p_Whh_l,
                                                    Ll * TO * Oo);
    split_elem<<<(Nn * Bb * Ff + 255) / 256, 256>>>(inputs, p_xh, p_xl,
                                                    Nn * Bb * Ff);
    transpose_split<<<dim3(4, 4, Ll * Dd), dim3(32, 8)>>>(W, p_WT_h, p_WT_l);
    transpose_split<<<dim3(4, 4, Ll), dim3(32, 8)>>>(Wh, p_WhT_h, p_WhT_l);

    for (int l = 0; l < Ll; l++) {
        const float* xin = (l == 0) ? inputs : p_x;
        float* xout = (l == Ll - 1) ? (float*)d_out : p_x;

        // support[d,b,n,o] = x @ W[l,d] + Bc[l,d]   (scatter, z=d)
        hmma_gemm<1, true, false><<<dim3(1, (Nn * Bb) / 128, Dd), 256, HG_SMEM>>>(
            p_xh, p_xl, 0,
            p_WT_h + (size_t)l * Dd * Oo * Ff, p_WT_l + (size_t)l * Dd * Oo * Ff,
            (size_t)Oo * Ff,
            Bc + (size_t)l * Dd * Oo, Oo, p_sup, 0, nullptr, nullptr, Oo, Ff);

        // supT hi/lo bf16 [db][o][n]
        sup_splitT<<<dim3(Nn / 32, Oo / 32, DB), dim3(32, 8)>>>(p_sup);

        // agg[db] = adj[db] @ supT[db]^T   -> bf16 hi/lo out (feeds gi)
        hmma_gemm<2, false, false><<<dim3(1, Nn / 128, DB), 256, HG_SMEM>>>(
            p_adjh, p_adjl, (size_t)Nn * Nn, p_supTh, p_supTl, (size_t)Oo * Nn,
            nullptr, 0, nullptr, (size_t)Nn * Oo, p_aggh, p_aggl, Oo, Nn);

        // gi = agg @ Wih^T + bih
        hmma_gemm<0, true, false><<<dim3(TO / 128, (DB * Nn) / 128, 1), 256, HG_SMEM>>>(
            p_aggh, p_aggl, 0,
            p_Wih_h + (size_t)l * TO * Oo, p_Wih_l + (size_t)l * TO * Oo, 0,
            bih + (size_t)l * TO, 0, p_gi, 0, nullptr, nullptr, TO, Oo);

        // gh = x @ Whh^T + bhh (once, shared across d)
        hmma_gemm<0, true, false><<<dim3(TO / 128, (Nn * Bb) / 128, 1), 256, HG_SMEM>>>(
            p_xh, p_xl, 0,
            p_Whh_h + (size_t)l * TO * Oo, p_Whh_l + (size_t)l * TO * Oo, 0,
            bhh + (size_t)l * TO, 0, p_gh, 0, nullptr, nullptr, TO, Oo);

        // t = relu(x @ Wh + Bh)
        hmma_gemm<0, true, true><<<dim3(1, (Nn * Bb) / 128, 1), 256, HG_SMEM>>>(
            p_xh, p_xl, 0,
            p_WhT_h + (size_t)l * Oo * Ff, p_WhT_l + (size_t)l * Oo * Ff, 0,
            Bh + (size_t)l * Oo, 0, p_t, 0, nullptr, nullptr, Oo, Ff);

        // fused GRU + sum_d + relu + highway (+ emit next layer's x splits)
        gru_highway<<<(Nn * Bb * Oo) / 256, 256>>>(
            xin, p_gi, p_gh, p_t, xout, p_xh, p_xl, (l < Ll - 1) ? 1 : 0);
    }
}

// round 10
// speedup vs baseline: 1.7042x; 1.0860x over previous
#include <cuda_runtime.h>
#include <cuda_bf16.h>
#include <math.h>
#include <stdint.h>

#define Nn 1024
#define Bb 8
#define Ff 128
#define Oo 128
#define Dd 3
#define Ll 2
#define TO 384  // 3*Oo
#define DB (Dd * Bb)

typedef __nv_bfloat16 bf16;

// ---------------- scratch (device globals: allocation-free) ----------------
__device__ float g_x[(size_t)Nn * Bb * Ff];
__device__ float g_support[(size_t)DB * Nn * Oo];
__device__ float g_gi[(size_t)DB * Nn * TO];
__device__ float g_gh[(size_t)Nn * Bb * TO];
__device__ float g_t[(size_t)Nn * Bb * Oo];
__device__ __align__(256) bf16 g_adjh[(size_t)DB * Nn * Nn];
__device__ __align__(256) bf16 g_adjl[(size_t)DB * Nn * Nn];
__device__ __align__(256) bf16 g_supTh[(size_t)DB * Oo * Nn];
__device__ __align__(256) bf16 g_supTl[(size_t)DB * Oo * Nn];
__device__ __align__(256) bf16 g_aggh[(size_t)DB * Nn * Oo];
__device__ __align__(256) bf16 g_aggl[(size_t)DB * Nn * Oo];
__device__ __align__(256) bf16 g_xh[(size_t)Nn * Bb * Ff];
__device__ __align__(256) bf16 g_xl[(size_t)Nn * Bb * Ff];
__device__ __align__(256) bf16 g_Wih_h[Ll * TO * Oo], g_Wih_l[Ll * TO * Oo];
__device__ __align__(256) bf16 g_Whh_h[Ll * TO * Oo], g_Whh_l[Ll * TO * Oo];
__device__ __align__(256) bf16 g_WT_h[Ll * Dd * Oo * Ff], g_WT_l[Ll * Dd * Oo * Ff];
__device__ __align__(256) bf16 g_WhT_h[Ll * Oo * Ff], g_WhT_l[Ll * Oo * Ff];

__device__ __forceinline__ uint32_t smem_u32(const void* p) {
    uint32_t a;
    asm("{ .reg .u64 t; cvta.to.shared.u64 t, %1; cvt.u32.u64 %0, t; }"
        : "=r"(a) : "l"(p));
    return a;
}

#define LDMX4(r, addr)                                                        \
    asm volatile("ldmatrix.sync.aligned.m8n8.x4.shared.b16 {%0,%1,%2,%3}, [%4];" \
                 : "=r"((r)[0]), "=r"((r)[1]), "=r"((r)[2]), "=r"((r)[3])     \
                 : "r"(addr))

#define MMA16816(c, a, b)                                                     \
    asm volatile(                                                             \
        "mma.sync.aligned.m16n8k16.row.col.f32.bf16.bf16.f32 "                \
        "{%0,%1,%2,%3}, {%4,%5,%6,%7}, {%8,%9}, {%0,%1,%2,%3};"               \
        : "+f"((c)[0]), "+f"((c)[1]), "+f"((c)[2]), "+f"((c)[3])              \
        : "r"((a)[0]), "r"((a)[1]), "r"((a)[2]), "r"((a)[3]),                 \
          "r"((b)[0]), "r"((b)[1]))

__device__ __forceinline__ void cp16(uint32_t saddr, const void* g) {
    asm volatile("cp.async.cg.shared.global [%0], [%1], 16;" ::"r"(saddr),
                 "l"(g));
}
#define CP_COMMIT() asm volatile("cp.async.commit_group;" ::: "memory")

__device__ __forceinline__ void split2(float v, bf16& h, bf16& l) {
    h = __float2bfloat16(v);
    l = __float2bfloat16(v - __bfloat162float(h));
}

// ---------------- prep kernels ---------------------------------------------
__global__ void split_elem(const float* __restrict__ src, bf16* __restrict__ h,
                           bf16* __restrict__ l, int count) {
    int i = blockIdx.x * blockDim.x + threadIdx.x;
    if (i >= count) return;
    split2(src[i], h[i], l[i]);
}

// batched 128x128 transpose + split: src [z][R=128][C=128] -> dst [z][C][R]
__global__ void transpose_split(const float* __restrict__ src,
                                bf16* __restrict__ dh, bf16* __restrict__ dl) {
    __shared__ float tile[32][33];
    const int z = blockIdx.z, r0 = blockIdx.x * 32, c0 = blockIdx.y * 32;
    const int tx = threadIdx.x, ty = threadIdx.y;
    const float* s = src + (size_t)z * 128 * 128;
#pragma unroll
    for (int r = 0; r < 4; r++)
        tile[ty + r * 8][tx] = s[(size_t)(r0 + ty + r * 8) * 128 + c0 + tx];
    __syncthreads();
    const size_t ob = (size_t)z * 128 * 128;
#pragma unroll
    for (int r = 0; r < 4; r++) {
        int c = c0 + ty + r * 8;
        bf16 h, l;
        split2(tile[tx][ty + r * 8], h, l);
        dh[ob + (size_t)c * 128 + r0 + tx] = h;
        dl[ob + (size_t)c * 128 + r0 + tx] = l;
    }
}

// ---------------- adj fp32 -> bf16 hi/lo split (once per call) --------------
__global__ void adj_split(const float4* __restrict__ adj) {
    size_t i = (size_t)blockIdx.x * blockDim.x + threadIdx.x;
    if (i >= (size_t)DB * Nn * Nn / 4) return;
    float4 a = adj[i];
    __nv_bfloat162 h01 = __floats2bfloat162_rn(a.x, a.y);
    __nv_bfloat162 h23 = __floats2bfloat162_rn(a.z, a.w);
    __nv_bfloat162 l01 = __floats2bfloat162_rn(a.x - __low2float(h01),
                                               a.y - __high2float(h01));
    __nv_bfloat162 l23 = __floats2bfloat162_rn(a.z - __low2float(h23),
                                               a.w - __high2float(h23));
    ((__nv_bfloat162*)g_adjh)[i * 2 + 0] = h01;
    ((__nv_bfloat162*)g_adjh)[i * 2 + 1] = h23;
    ((__nv_bfloat162*)g_adjl)[i * 2 + 0] = l01;
    ((__nv_bfloat162*)g_adjl)[i * 2 + 1] = l23;
}

// ------- support [db][n][o] fp32 -> transposed bf16 hi/lo [db][o][n] -------
__global__ void sup_splitT(const float* __restrict__ sup) {
    __shared__ float tile[32][33];
    const int db = blockIdx.z, n0 = blockIdx.x * 32, o0 = blockIdx.y * 32;
    const int tx = threadIdx.x, ty = threadIdx.y;
    const float* s = sup + (size_t)db * Nn * Oo;
#pragma unroll
    for (int r = 0; r < 4; r++)
        tile[ty + r * 8][tx] = s[(size_t)(n0 + ty + r * 8) * Oo + o0 + tx];
    __syncthreads();
    const size_t ob = (size_t)db * Oo * Nn;
#pragma unroll
    for (int r = 0; r < 4; r++) {
        int o = o0 + ty + r * 8;
        bf16 h, l;
        split2(tile[tx][ty + r * 8], h, l);
        g_supTh[ob + (size_t)o * Nn + n0 + tx] = h;
        g_supTl[ob + (size_t)o * Nn + n0 + tx] = l;
    }
}

// ================= unified split-bf16 HMMA GEMM (cp.async pipelined) =======
// C[M,N] = A[M,K] @ B[N,K]^T  (operands pre-split bf16 hi/lo, K-major)
// D += Ah*Bh + Ah*Bl + Al*Bh  (fp32 accumulate; ~fp32 precision)
// CTA tile 128x128, K chunks of 64, double-buffered via cp.async.
// 8 warps (4 M x 2 N), 32x64 warp tile.
#define PITCH 72
#define TILE_B (128 * PITCH * 2)   // 18432 bytes per tile
#define STAGE_B (4 * TILE_B)       // 73728 per stage
#define HG_SMEM (2 * STAGE_B)      // 147456

template <int OUT_MODE, bool BIAS, bool RELU>
__global__ __launch_bounds__(256)
void hmma_gemm(const bf16* __restrict__ Ah_, const bf16* __restrict__ Al_,
               size_t strideAz,
               const bf16* __restrict__ Bh_, const bf16* __restrict__ Bl_,
               size_t strideBz,
               const float* __restrict__ bias, int biasStrideZ,
               float* __restrict__ C, size_t strideCz,
               bf16* __restrict__ Ch, bf16* __restrict__ Cl,
               int Ncols, int K) {
    extern __shared__ bf16 smem[];
    const uint32_t sbase = smem_u32(smem);

    const int tid = threadIdx.x, wid = tid >> 5, lane = tid & 31;
    const int n0 = blockIdx.x * 128, m0 = blockIdx.y * 128, z = blockIdx.z;
    const int wm0 = (wid & 3) * 32;
    const int wn0 = (wid >> 2) * 64;

    const bf16* Ah = Ah_ + (size_t)z * strideAz + (size_t)m0 * K;
    const bf16* Al = Al_ + (size_t)z * strideAz + (size_t)m0 * K;
    const bf16* Bh = Bh_ + (size_t)z * strideBz + (size_t)n0 * K;
    const bf16* Bl = Bl_ + (size_t)z * strideBz + (size_t)n0 * K;

    // per-thread staging coords (16B per cp.async, 16 copies/thread/chunk)
    const int sRow[4] = {tid >> 3, (tid + 256) >> 3, (tid + 512) >> 3,
                         (tid + 768) >> 3};
    const int sGrp = tid & 7;
    const uint32_t sOffBase = sGrp * 16;

    float acc[2][8][4];
#pragma unroll
    for (int i = 0; i < 2; i++)
#pragma unroll
        for (int j = 0; j < 8; j++)
#pragma unroll
            for (int q = 0; q < 4; q++) acc[i][j][q] = 0.f;

    const uint32_t lrow = lane & 15;
    const uint32_t lcg = (lane >> 4) * 16;
    const int chunks = K >> 6;

    // ---- prefetch chunk 0 into stage 0 ----
    {
        const uint32_t st = sbase;
#pragma unroll
        for (int k = 0; k < 4; k++) {
            const int row = sRow[k];
            const uint32_t so = row * (PITCH * 2) + sOffBase;
            const size_t go = (size_t)row * K + sGrp * 8;
            cp16(st + so, Ah + go);
            cp16(st + TILE_B + so, Al + go);
            cp16(st + 2 * TILE_B + so, Bh + go);
            cp16(st + 3 * TILE_B + so, Bl + go);
        }
        CP_COMMIT();
    }

    for (int c = 0; c < chunks; c++) {
        if (c + 1 < chunks) {
            const uint32_t st = sbase + ((c + 1) & 1) * STAGE_B;
            const int koff = (c + 1) * 64;
#pragma unroll
            for (int k = 0; k < 4; k++) {
                const int row = sRow[k];
                const uint32_t so = row * (PITCH * 2) + sOffBase;
                const size_t go = (size_t)row * K + koff + sGrp * 8;
                cp16(st + so, Ah + go);
                cp16(st + TILE_B + so, Al + go);
                cp16(st + 2 * TILE_B + so, Bh + go);
                cp16(st + 3 * TILE_B + so, Bl + go);
            }
            CP_COMMIT();
            asm volatile("cp.async.wait_group 1;" ::: "memory");
        } else {
            asm volatile("cp.async.wait_group 0;" ::: "memory");
        }
        __syncthreads();

        const uint32_t sAh = sbase + (c & 1) * STAGE_B;
        const uint32_t sAl = sAh + TILE_B;
        const uint32_t sBh = sAh + 2 * TILE_B;
        const uint32_t sBl = sAh + 3 * TILE_B;

#pragma unroll
        for (int ks = 0; ks < 4; ks++) {
            const uint32_t kb = ks * 32 + lcg;
            uint32_t a_h[2][4], a_l[2][4];
#pragma unroll
            for (int i = 0; i < 2; i++) {
                const uint32_t ro = (wm0 + i * 16 + lrow) * (PITCH * 2) + kb;
                LDMX4(a_h[i], sAh + ro);
                LDMX4(a_l[i], sAl + ro);
            }
            uint32_t b_h[8][2], b_l[8][2];
#pragma unroll
            for (int j2 = 0; j2 < 4; j2++) {
                const uint32_t ro = (wn0 + j2 * 16 + lrow) * (PITCH * 2) + kb;
                uint32_t rh[4], rl[4];
                LDMX4(rh, sBh + ro);
                LDMX4(rl, sBl + ro);
                b_h[2 * j2][0] = rh[0]; b_h[2 * j2][1] = rh[2];
                b_h[2 * j2 + 1][0] = rh[1]; b_h[2 * j2 + 1][1] = rh[3];
                b_l[2 * j2][0] = rl[0]; b_l[2 * j2][1] = rl[2];
                b_l[2 * j2 + 1][0] = rl[1]; b_l[2 * j2 + 1][1] = rl[3];
            }
#pragma unroll
            for (int i = 0; i < 2; i++)
#pragma unroll
                for (int j = 0; j < 8; j++) {
                    MMA16816(acc[i][j], a_h[i], b_h[j]);
                    MMA16816(acc[i][j], a_h[i], b_l[j]);
                    MMA16816(acc[i][j], a_l[i], b_h[j]);
                }
        }
        __syncthreads();
    }

    // ----- epilogue -----
    const int g = lane >> 2, t2 = (lane & 3) * 2;
#pragma unroll
    for (int i = 0; i < 2; i++) {
#pragma unroll
        for (int half = 0; half < 2; half++) {
            const int rloc = wm0 + i * 16 + half * 8 + g;  // 0..127
#pragma unroll
            for (int j = 0; j < 8; j++) {
                const int col = n0 + wn0 + j * 8 + t2;
                float v0 = acc[i][j][half * 2 + 0];
                float v1 = acc[i][j][half * 2 + 1];
                if (BIAS) {
                    const float* bz = bias + (size_t)biasStrideZ * z;
                    v0 += bz[col];
                    v1 += bz[col + 1];
                }
                if (RELU) { v0 = fmaxf(v0, 0.f); v1 = fmaxf(v1, 0.f); }
                if (OUT_MODE == 0) {
                    const size_t o = (size_t)z * strideCz +
                                     (size_t)(m0 + rloc) * Ncols + col;
                    *(float2*)(C + o) = make_float2(v0, v1);
                } else if (OUT_MODE == 1) {
                    const int row = m0 + rloc;
                    const int b = row & 7, n = row >> 3;
                    const size_t o = (((size_t)z * Bb + b) * Nn + n) * Oo + col;
                    *(float2*)(C + o) = make_float2(v0, v1);
                } else {
                    bf16 h0, l0, h1, l1;
                    split2(v0, h0, l0);
                    split2(v1, h1, l1);
                    const size_t o = (size_t)z * strideCz +
                                     (size_t)(m0 + rloc) * 128 + col;
                    *(__nv_bfloat162*)(Ch + o) = __nv_bfloat162(h0, h1);
                    *(__nv_bfloat162*)(Cl + o) = __nv_bfloat162(l0, l1);
                }
            }
        }
    }
}

// ---------------- fused GRU (sum over d) + relu + highway ------------------
__global__ void gru_highway(const float* __restrict__ x,
                            const float* __restrict__ gi,
                            const float* __restrict__ gh,
                            const float* __restrict__ t,
                            float* __restrict__ xout,
                            bf16* __restrict__ xh, bf16* __restrict__ xl,
                            int writeSplit) {
    const int idx = blockIdx.x * blockDim.x + threadIdx.x;
    const int o = idx & (Oo - 1);
    const int r = idx >> 7;
    const int b = r & (Bb - 1);
    const int n = r >> 3;

    const float xv = x[idx];
    const float tv = t[idx];
    const size_t ghb = (size_t)r * TO;
    const float hr = gh[ghb + o];
    const float hz = gh[ghb + Oo + o];
    const float hn = gh[ghb + 2 * Oo + o];

    float sum = 0.f;
#pragma unroll
    for (int d = 0; d < Dd; d++) {
        const size_t gb = ((size_t)(d * Bb + b) * Nn + n) * TO;
        const float ir = gi[gb + o];
        const float iz = gi[gb + Oo + o];
        const float in_ = gi[gb + 2 * Oo + o];
        const float rg = 1.f / (1.f + expf(-(ir + hr)));
        const float zg = 1.f / (1.f + expf(-(iz + hz)));
        const float ng = tanhf(in_ + rg * hn);
        sum += (1.f - zg) * ng + zg * xv;
    }
    sum = fmaxf(sum, 0.f);
    const float out = sum * tv + xv * (1.f - tv);
    xout[idx] = out;
    if (writeSplit) {
        bf16 h, l;
        split2(out, h, l);
        xh[idx] = h;
        xl[idx] = l;
    }
}

// ---------------- launch ---------------------------------------------------
extern "C" void kernel_launch(void* const* d_in, const int* in_sizes, int n_in,
                              void* d_out, int out_size) {
    const float* inputs = (const float*)d_in[0];
    const float* adj    = (const float*)d_in[1];
    const float* W      = (const float*)d_in[2];
    const float* Bc     = (const float*)d_in[3];
    const float* Wh     = (const float*)d_in[4];
    const float* Bh     = (const float*)d_in[5];
    const float* Wih    = (const float*)d_in[6];
    const float* Whh    = (const float*)d_in[7];
    const float* bih    = (const float*)d_in[8];
    const float* bhh    = (const float*)d_in[9];

    float *p_x, *p_sup, *p_gi, *p_gh, *p_t;
    bf16 *p_adjh, *p_adjl, *p_supTh, *p_supTl, *p_aggh, *p_aggl, *p_xh, *p_xl;
    bf16 *p_Wih_h, *p_Wih_l, *p_Whh_h, *p_Whh_l, *p_WT_h, *p_WT_l, *p_WhT_h, *p_WhT_l;
    cudaGetSymbolAddress((void**)&p_x, g_x);
    cudaGetSymbolAddress((void**)&p_sup, g_support);
    cudaGetSymbolAddress((void**)&p_gi, g_gi);
    cudaGetSymbolAddress((void**)&p_gh, g_gh);
    cudaGetSymbolAddress((void**)&p_t, g_t);
    cudaGetSymbolAddress((void**)&p_adjh, g_adjh);
    cudaGetSymbolAddress((void**)&p_adjl, g_adjl);
    cudaGetSymbolAddress((void**)&p_supTh, g_supTh);
    cudaGetSymbolAddress((void**)&p_supTl, g_supTl);
    cudaGetSymbolAddress((void**)&p_aggh, g_aggh);
    cudaGetSymbolAddress((void**)&p_aggl, g_aggl);
    cudaGetSymbolAddress((void**)&p_xh, g_xh);
    cudaGetSymbolAddress((void**)&p_xl, g_xl);
    cudaGetSymbolAddress((void**)&p_Wih_h, g_Wih_h);
    cudaGetSymbolAddress((void**)&p_Wih_l, g_Wih_l);
    cudaGetSymbolAddress((void**)&p_Whh_h, g_Whh_h);
    cudaGetSymbolAddress((void**)&p_Whh_l, g_Whh_l);
    cudaGetSymbolAddress((void**)&p_WT_h, g_WT_h);
    cudaGetSymbolAddress((void**)&p_WT_l, g_WT_l);
    cudaGetSymbolAddress((void**)&p_WhT_h, g_WhT_h);
    cudaGetSymbolAddress((void**)&p_WhT_l, g_WhT_l);

    cudaFuncSetAttribute(hmma_gemm<0, true, false>,
                         cudaFuncAttributeMaxDynamicSharedMemorySize, HG_SMEM);
    cudaFuncSetAttribute(hmma_gemm<0, true, true>,
                         cudaFuncAttributeMaxDynamicSharedMemorySize, HG_SMEM);
    cudaFuncSetAttribute(hmma_gemm<1, true, false>,
                         cudaFuncAttributeMaxDynamicSharedMemorySize, HG_SMEM);
    cudaFuncSetAttribute(hmma_gemm<2, false, false>,
                         cudaFuncAttributeMaxDynamicSharedMemorySize, HG_SMEM);

    // ---- one-time prep ----
    adj_split<<<(int)(((size_t)DB * Nn * Nn / 4 + 255) / 256), 256>>>(
        (const float4*)adj);
    split_elem<<<(Ll * TO * Oo + 255) / 256, 256>>>(Wih, p_Wih_h, p_Wih_l,
                                                    Ll * TO * Oo);
    split_elem<<<(Ll * TO * Oo + 255) / 256, 256>>>(Whh, p_Whh_h, p_Whh_l,
                                                    Ll * TO * Oo);
    split_elem<<<(Nn * Bb * Ff + 255) / 256, 256>>>(inputs, p_xh, p_xl,
                                                    Nn * Bb * Ff);
    transpose_split<<<dim3(4, 4, Ll * Dd), dim3(32, 8)>>>(W, p_WT_h, p_WT_l);
    transpose_split<<<dim3(4, 4, Ll), dim3(32, 8)>>>(Wh, p_WhT_h, p_WhT_l);

    for (int l = 0; l < Ll; l++) {
        const float* xin = (l == 0) ? inputs : p_x;
        float* xout = (l == Ll - 1) ? (float*)d_out : p_x;

        // support[d,b,n,o] = x @ W[l,d] + Bc[l,d]   (scatter, z=d)
        hmma_gemm<1, true, false><<<dim3(1, (Nn * Bb) / 128, Dd), 256, HG_SMEM>>>(
            p_xh, p_xl, 0,
            p_WT_h + (size_t)l * Dd * Oo * Ff, p_WT_l + (size_t)l * Dd * Oo * Ff,
            (size_t)Oo * Ff,
            Bc + (size_t)l * Dd * Oo, Oo, p_sup, 0, nullptr, nullptr, Oo, Ff);

        // supT hi/lo bf16 [db][o][n]
        sup_splitT<<<dim3(Nn / 32, Oo / 32, DB), dim3(32, 8)>>>(p_sup);

        // agg[db] = adj[db] @ supT[db]^T   -> bf16 hi/lo out (feeds gi)
        hmma_gemm<2, false, false><<<dim3(1, Nn / 128, DB), 256, HG_SMEM>>>(
            p_adjh, p_adjl, (size_t)Nn * Nn, p_supTh, p_supTl, (size_t)Oo * Nn,
            nullptr, 0, nullptr, (size_t)Nn * Oo, p_aggh, p_aggl, Oo, Nn);

        // gi = agg @ Wih^T + bih
        hmma_gemm<0, true, false><<<dim3(TO / 128, (DB * Nn) / 128, 1), 256, HG_SMEM>>>(
            p_aggh, p_aggl, 0,
            p_Wih_h + (size_t)l * TO * Oo, p_Wih_l + (size_t)l * TO * Oo, 0,
            bih + (size_t)l * TO, 0, p_gi, 0, nullptr, nullptr, TO, Oo);

        // gh = x @ Whh^T + bhh (once, shared across d)
        hmma_gemm<0, true, false><<<dim3(TO / 128, (Nn * Bb) / 128, 1), 256, HG_SMEM>>>(
            p_xh, p_xl, 0,
            p_Whh_h + (size_t)l * TO * Oo, p_Whh_l + (size_t)l * TO * Oo, 0,
            bhh + (size_t)l * TO, 0, p_gh, 0, nullptr, nullptr, TO, Oo);

        // t = relu(x @ Wh + Bh)
        hmma_gemm<0, true, true><<<dim3(1, (Nn * Bb) / 128, 1), 256, HG_SMEM>>>(
            p_xh, p_xl, 0,
            p_WhT_h + (size_t)l * Oo * Ff, p_WhT_l + (size_t)l * Oo * Ff, 0,
            Bh + (size_t)l * Oo, 0, p_t, 0, nullptr, nullptr, Oo, Ff);

        // fused GRU + sum_d + relu + highway (+ emit next layer's x splits)
        gru_highway<<<(Nn * Bb * Oo) / 256, 256>>>(
            xin, p_gi, p_gh, p_t, xout, p_xh, p_xl, (l < Ll - 1) ? 1 : 0);
    }
}

// round 11
// speedup vs baseline: 1.8336x; 1.0759x over previous
#include <cuda_runtime.h>
#include <cuda_bf16.h>
#include <math.h>
#include <stdint.h>

#define Nn 1024
#define Bb 8
#define Ff 128
#define Oo 128
#define Dd 3
#define Ll 2
#define TO 384   // 3*Oo
#define DB (Dd * Bb)
#define NCAT 896 // 3*128 (support) + 384 (gh) + 128 (t)

typedef __nv_bfloat16 bf16;

// ---------------- scratch (device globals: allocation-free) ----------------
__device__ float g_x[(size_t)Nn * Bb * Ff];
__device__ float g_support[(size_t)DB * Nn * Oo];
__device__ float g_gi[(size_t)DB * Nn * TO];
__device__ float g_gh[(size_t)Nn * Bb * TO];
__device__ float g_t[(size_t)Nn * Bb * Oo];
__device__ __align__(256) bf16 g_adjh[(size_t)DB * Nn * Nn];
__device__ __align__(256) bf16 g_adjl[(size_t)DB * Nn * Nn];
__device__ __align__(256) bf16 g_supTh[(size_t)DB * Oo * Nn];
__device__ __align__(256) bf16 g_supTl[(size_t)DB * Oo * Nn];
__device__ __align__(256) bf16 g_aggh[(size_t)DB * Nn * Oo];
__device__ __align__(256) bf16 g_aggl[(size_t)DB * Nn * Oo];
__device__ __align__(256) bf16 g_xh[(size_t)Nn * Bb * Ff];
__device__ __align__(256) bf16 g_xl[(size_t)Nn * Bb * Ff];
__device__ __align__(256) bf16 g_Wih_h[Ll * TO * Oo], g_Wih_l[Ll * TO * Oo];
__device__ __align__(256) bf16 g_Wcat_h[(size_t)Ll * NCAT * Ff];
__device__ __align__(256) bf16 g_Wcat_l[(size_t)Ll * NCAT * Ff];
__device__ float g_cbias[Ll * NCAT];

__device__ __forceinline__ uint32_t smem_u32(const void* p) {
    uint32_t a;
    asm("{ .reg .u64 t; cvta.to.shared.u64 t, %1; cvt.u32.u64 %0, t; }"
        : "=r"(a) : "l"(p));
    return a;
}

#define LDMX4(r, addr)                                                        \
    asm volatile("ldmatrix.sync.aligned.m8n8.x4.shared.b16 {%0,%1,%2,%3}, [%4];" \
                 : "=r"((r)[0]), "=r"((r)[1]), "=r"((r)[2]), "=r"((r)[3])     \
                 : "r"(addr))

#define MMA16816(c, a, b)                                                     \
    asm volatile(                                                             \
        "mma.sync.aligned.m16n8k16.row.col.f32.bf16.bf16.f32 "                \
        "{%0,%1,%2,%3}, {%4,%5,%6,%7}, {%8,%9}, {%0,%1,%2,%3};"               \
        : "+f"((c)[0]), "+f"((c)[1]), "+f"((c)[2]), "+f"((c)[3])              \
        : "r"((a)[0]), "r"((a)[1]), "r"((a)[2]), "r"((a)[3]),                 \
          "r"((b)[0]), "r"((b)[1]))

__device__ __forceinline__ void cp16(uint32_t saddr, const void* g) {
    asm volatile("cp.async.cg.shared.global [%0], [%1], 16;" ::"r"(saddr),
                 "l"(g));
}
#define CP_COMMIT() asm volatile("cp.async.commit_group;" ::: "memory")

__device__ __forceinline__ void split2(float v, bf16& h, bf16& l) {
    h = __float2bfloat16(v);
    l = __float2bfloat16(v - __bfloat162float(h));
}

// ---------------- prep kernels ---------------------------------------------
__global__ void split_elem(const float* __restrict__ src, bf16* __restrict__ h,
                           bf16* __restrict__ l, int count) {
    int i = blockIdx.x * blockDim.x + threadIdx.x;
    if (i >= count) return;
    split2(src[i], h[i], l[i]);
}

// build concatenated weight [l][c(896)][k(128)] K-major + bias
__global__ void concat_w(const float* __restrict__ W,
                         const float* __restrict__ Whh,
                         const float* __restrict__ Wh,
                         const float* __restrict__ Bc,
                         const float* __restrict__ bhh,
                         const float* __restrict__ Bh) {
    int idx = blockIdx.x * blockDim.x + threadIdx.x;
    if (idx >= Ll * NCAT * Ff) return;
    const int k = idx & 127;
    const int c = (idx >> 7) % NCAT;
    const int l = idx / (NCAT * Ff);
    float v;
    if (c < 384) {
        const int d = c >> 7, o = c & 127;
        v = W[(((size_t)l * Dd + d) * Ff + k) * Oo + o];
    } else if (c < 768) {
        v = Whh[((size_t)l * TO + (c - 384)) * Oo + k];
    } else {
        v = Wh[((size_t)l * Ff + k) * Oo + (c - 768)];
    }
    bf16 h, lo;
    split2(v, h, lo);
    g_Wcat_h[idx] = h;
    g_Wcat_l[idx] = lo;
    if (k == 0) {
        float bv = (c < 384) ? Bc[(l * Dd + (c >> 7)) * Oo + (c & 127)]
                 : (c < 768) ? bhh[l * TO + (c - 384)]
                             : Bh[l * Oo + (c - 768)];
        g_cbias[l * NCAT + c] = bv;
    }
}

// ---------------- adj fp32 -> bf16 hi/lo split (once per call) --------------
__global__ void adj_split(const float4* __restrict__ adj) {
    size_t i = (size_t)blockIdx.x * blockDim.x + threadIdx.x;
    if (i >= (size_t)DB * Nn * Nn / 4) return;
    float4 a = adj[i];
    __nv_bfloat162 h01 = __floats2bfloat162_rn(a.x, a.y);
    __nv_bfloat162 h23 = __floats2bfloat162_rn(a.z, a.w);
    __nv_bfloat162 l01 = __floats2bfloat162_rn(a.x - __low2float(h01),
                                               a.y - __high2float(h01));
    __nv_bfloat162 l23 = __floats2bfloat162_rn(a.z - __low2float(h23),
                                               a.w - __high2float(h23));
    ((__nv_bfloat162*)g_adjh)[i * 2 + 0] = h01;
    ((__nv_bfloat162*)g_adjh)[i * 2 + 1] = h23;
    ((__nv_bfloat162*)g_adjl)[i * 2 + 0] = l01;
    ((__nv_bfloat162*)g_adjl)[i * 2 + 1] = l23;
}

// ------- support [db][n][o] fp32 -> transposed bf16 hi/lo [db][o][n] -------
__global__ void sup_splitT(const float* __restrict__ sup) {
    __shared__ float tile[32][33];
    const int db = blockIdx.z, n0 = blockIdx.x * 32, o0 = blockIdx.y * 32;
    const int tx = threadIdx.x, ty = threadIdx.y;
    const float* s = sup + (size_t)db * Nn * Oo;
#pragma unroll
    for (int r = 0; r < 4; r++)
        tile[ty + r * 8][tx] = s[(size_t)(n0 + ty + r * 8) * Oo + o0 + tx];
    __syncthreads();
    const size_t ob = (size_t)db * Oo * Nn;
#pragma unroll
    for (int r = 0; r < 4; r++) {
        int o = o0 + ty + r * 8;
        bf16 h, l;
        split2(tile[tx][ty + r * 8], h, l);
        g_supTh[ob + (size_t)o * Nn + n0 + tx] = h;
        g_supTl[ob + (size_t)o * Nn + n0 + tx] = l;
    }
}

// ================= unified split-bf16 HMMA GEMM (cp.async pipelined) =======
// C[M,N] = A[M,K] @ B[N,K]^T  (operands pre-split bf16 hi/lo, K-major)
// D += Ah*Bh + Ah*Bl + Al*Bh  (fp32 accumulate; ~fp32 precision)
// CTA tile 128x128, K chunks of 64, double-buffered cp.async.
// OUT_MODE 0: fp32 C[z*strideCz + row*Ncols + col]
// OUT_MODE 2: bf16 hi/lo split out (Ch/Cl), row-major 128 cols
// OUT_MODE 3: combined routing (support scatter | gh | t+relu), bias = cbias
#define PITCH 72
#define TILE_B (128 * PITCH * 2)   // 18432 bytes per tile
#define STAGE_B (4 * TILE_B)       // 73728 per stage
#define HG_SMEM (2 * STAGE_B)      // 147456

template <int OUT_MODE, bool BIAS, bool RELU>
__global__ __launch_bounds__(256)
void hmma_gemm(const bf16* __restrict__ Ah_, const bf16* __restrict__ Al_,
               size_t strideAz,
               const bf16* __restrict__ Bh_, const bf16* __restrict__ Bl_,
               size_t strideBz,
               const float* __restrict__ bias, int biasStrideZ,
               float* __restrict__ C, size_t strideCz,
               bf16* __restrict__ Ch, bf16* __restrict__ Cl,
               float* __restrict__ C2, float* __restrict__ C3,
               int Ncols, int K) {
    extern __shared__ bf16 smem[];
    const uint32_t sbase = smem_u32(smem);

    const int tid = threadIdx.x, wid = tid >> 5, lane = tid & 31;
    const int n0 = blockIdx.x * 128, m0 = blockIdx.y * 128, z = blockIdx.z;
    const int wm0 = (wid & 3) * 32;
    const int wn0 = (wid >> 2) * 64;

    const bf16* Ah = Ah_ + (size_t)z * strideAz + (size_t)m0 * K;
    const bf16* Al = Al_ + (size_t)z * strideAz + (size_t)m0 * K;
    const bf16* Bh = Bh_ + (size_t)z * strideBz + (size_t)n0 * K;
    const bf16* Bl = Bl_ + (size_t)z * strideBz + (size_t)n0 * K;

    const int sRow[4] = {tid >> 3, (tid + 256) >> 3, (tid + 512) >> 3,
                         (tid + 768) >> 3};
    const int sGrp = tid & 7;
    const uint32_t sOffBase = sGrp * 16;

    float acc[2][8][4];
#pragma unroll
    for (int i = 0; i < 2; i++)
#pragma unroll
        for (int j = 0; j < 8; j++)
#pragma unroll
            for (int q = 0; q < 4; q++) acc[i][j][q] = 0.f;

    const uint32_t lrow = lane & 15;
    const uint32_t lcg = (lane >> 4) * 16;
    const int chunks = K >> 6;

    {
        const uint32_t st = sbase;
#pragma unroll
        for (int k = 0; k < 4; k++) {
            const int row = sRow[k];
            const uint32_t so = row * (PITCH * 2) + sOffBase;
            const size_t go = (size_t)row * K + sGrp * 8;
            cp16(st + so, Ah + go);
            cp16(st + TILE_B + so, Al + go);
            cp16(st + 2 * TILE_B + so, Bh + go);
            cp16(st + 3 * TILE_B + so, Bl + go);
        }
        CP_COMMIT();
    }

    for (int c = 0; c < chunks; c++) {
        if (c + 1 < chunks) {
            const uint32_t st = sbase + ((c + 1) & 1) * STAGE_B;
            const int koff = (c + 1) * 64;
#pragma unroll
            for (int k = 0; k < 4; k++) {
                const int row = sRow[k];
                const uint32_t so = row * (PITCH * 2) + sOffBase;
                const size_t go = (size_t)row * K + koff + sGrp * 8;
                cp16(st + so, Ah + go);
                cp16(st + TILE_B + so, Al + go);
                cp16(st + 2 * TILE_B + so, Bh + go);
                cp16(st + 3 * TILE_B + so, Bl + go);
            }
            CP_COMMIT();
            asm volatile("cp.async.wait_group 1;" ::: "memory");
        } else {
            asm volatile("cp.async.wait_group 0;" ::: "memory");
        }
        __syncthreads();

        const uint32_t sAh = sbase + (c & 1) * STAGE_B;
        const uint32_t sAl = sAh + TILE_B;
        const uint32_t sBh = sAh + 2 * TILE_B;
        const uint32_t sBl = sAh + 3 * TILE_B;

#pragma unroll
        for (int ks = 0; ks < 4; ks++) {
            const uint32_t kb = ks * 32 + lcg;
            uint32_t a_h[2][4], a_l[2][4];
#pragma unroll
            for (int i = 0; i < 2; i++) {
                const uint32_t ro = (wm0 + i * 16 + lrow) * (PITCH * 2) + kb;
                LDMX4(a_h[i], sAh + ro);
                LDMX4(a_l[i], sAl + ro);
            }
            uint32_t b_h[8][2], b_l[8][2];
#pragma unroll
            for (int j2 = 0; j2 < 4; j2++) {
                const uint32_t ro = (wn0 + j2 * 16 + lrow) * (PITCH * 2) + kb;
                uint32_t rh[4], rl[4];
                LDMX4(rh, sBh + ro);
                LDMX4(rl, sBl + ro);
                b_h[2 * j2][0] = rh[0]; b_h[2 * j2][1] = rh[2];
                b_h[2 * j2 + 1][0] = rh[1]; b_h[2 * j2 + 1][1] = rh[3];
                b_l[2 * j2][0] = rl[0]; b_l[2 * j2][1] = rl[2];
                b_l[2 * j2 + 1][0] = rl[1]; b_l[2 * j2 + 1][1] = rl[3];
            }
#pragma unroll
            for (int i = 0; i < 2; i++)
#pragma unroll
                for (int j = 0; j < 8; j++) {
                    MMA16816(acc[i][j], a_h[i], b_h[j]);
                    MMA16816(acc[i][j], a_h[i], b_l[j]);
                    MMA16816(acc[i][j], a_l[i], b_h[j]);
                }
        }
        __syncthreads();
    }

    // ----- epilogue -----
    const int g = lane >> 2, t2 = (lane & 3) * 2;
#pragma unroll
    for (int i = 0; i < 2; i++) {
#pragma unroll
        for (int half = 0; half < 2; half++) {
            const int rloc = wm0 + i * 16 + half * 8 + g;  // 0..127
#pragma unroll
            for (int j = 0; j < 8; j++) {
                const int col = n0 + wn0 + j * 8 + t2;
                float v0 = acc[i][j][half * 2 + 0];
                float v1 = acc[i][j][half * 2 + 1];
                if (BIAS) {
                    const float* bz = bias + (size_t)biasStrideZ * z;
                    v0 += bz[col];
                    v1 += bz[col + 1];
                }
                if (RELU) { v0 = fmaxf(v0, 0.f); v1 = fmaxf(v1, 0.f); }
                const int row = m0 + rloc;
                if (OUT_MODE == 0) {
                    const size_t o = (size_t)z * strideCz +
                                     (size_t)row * Ncols + col;
                    *(float2*)(C + o) = make_float2(v0, v1);
                } else if (OUT_MODE == 2) {
                    bf16 h0, l0, h1, l1;
                    split2(v0, h0, l0);
                    split2(v1, h1, l1);
                    const size_t o = (size_t)z * strideCz +
                                     (size_t)row * 128 + col;
                    *(__nv_bfloat162*)(Ch + o) = __nv_bfloat162(h0, h1);
                    *(__nv_bfloat162*)(Cl + o) = __nv_bfloat162(l0, l1);
                } else {  // combined: [0,384) support | [384,768) gh | t
                    if (col < 384) {
                        const int d = col >> 7, o2 = col & 127;
                        const int b = row & 7, n = row >> 3;
                        const size_t o = (((size_t)(d * Bb + b)) * Nn + n) * Oo + o2;
                        *(float2*)(C + o) = make_float2(v0, v1);
                    } else if (col < 768) {
                        const size_t o = (size_t)row * TO + (col - 384);
                        *(float2*)(C2 + o) = make_float2(v0, v1);
                    } else {
                        const size_t o = (size_t)row * Oo + (col - 768);
                        *(float2*)(C3 + o) =
                            make_float2(fmaxf(v0, 0.f), fmaxf(v1, 0.f));
                    }
                }
            }
        }
    }
}

// ---------------- fused GRU (sum over d) + relu + highway ------------------
__global__ void gru_highway(const float* __restrict__ x,
                            const float* __restrict__ gi,
                            const float* __restrict__ gh,
                            const float* __restrict__ t,
                            float* __restrict__ xout,
                            bf16* __restrict__ xh, bf16* __restrict__ xl,
                            int writeSplit) {
    const int idx = blockIdx.x * blockDim.x + threadIdx.x;
    const int o = idx & (Oo - 1);
    const int r = idx >> 7;
    const int b = r & (Bb - 1);
    const int n = r >> 3;

    const float xv = x[idx];
    const float tv = t[idx];
    const size_t ghb = (size_t)r * TO;
    const float hr = gh[ghb + o];
    const float hz = gh[ghb + Oo + o];
    const float hn = gh[ghb + 2 * Oo + o];

    float sum = 0.f;
#pragma unroll
    for (int d = 0; d < Dd; d++) {
        const size_t gb = ((size_t)(d * Bb + b) * Nn + n) * TO;
        const float ir = gi[gb + o];
        const float iz = gi[gb + Oo + o];
        const float in_ = gi[gb + 2 * Oo + o];
        const float rg = 1.f / (1.f + expf(-(ir + hr)));
        const float zg = 1.f / (1.f + expf(-(iz + hz)));
        const float ng = tanhf(in_ + rg * hn);
        sum += (1.f - zg) * ng + zg * xv;
    }
    sum = fmaxf(sum, 0.f);
    const float out = sum * tv + xv * (1.f - tv);
    xout[idx] = out;
    if (writeSplit) {
        bf16 h, l;
        split2(out, h, l);
        xh[idx] = h;
        xl[idx] = l;
    }
}

// ---------------- launch ---------------------------------------------------
extern "C" void kernel_launch(void* const* d_in, const int* in_sizes, int n_in,
                              void* d_out, int out_size) {
    const float* inputs = (const float*)d_in[0];
    const float* adj    = (const float*)d_in[1];
    const float* W      = (const float*)d_in[2];
    const float* Bc     = (const float*)d_in[3];
    const float* Wh     = (const float*)d_in[4];
    const float* Bh     = (const float*)d_in[5];
    const float* Wih    = (const float*)d_in[6];
    const float* Whh    = (const float*)d_in[7];
    const float* bih    = (const float*)d_in[8];
    const float* bhh    = (const float*)d_in[9];

    float *p_x, *p_sup, *p_gi, *p_gh, *p_t, *p_cbias;
    bf16 *p_adjh, *p_adjl, *p_supTh, *p_supTl, *p_aggh, *p_aggl, *p_xh, *p_xl;
    bf16 *p_Wih_h, *p_Wih_l, *p_Wcat_h, *p_Wcat_l;
    cudaGetSymbolAddress((void**)&p_x, g_x);
    cudaGetSymbolAddress((void**)&p_sup, g_support);
    cudaGetSymbolAddress((void**)&p_gi, g_gi);
    cudaGetSymbolAddress((void**)&p_gh, g_gh);
    cudaGetSymbolAddress((void**)&p_t, g_t);
    cudaGetSymbolAddress((void**)&p_adjh, g_adjh);
    cudaGetSymbolAddress((void**)&p_adjl, g_adjl);
    cudaGetSymbolAddress((void**)&p_supTh, g_supTh);
    cudaGetSymbolAddress((void**)&p_supTl, g_supTl);
    cudaGetSymbolAddress((void**)&p_aggh, g_aggh);
    cudaGetSymbolAddress((void**)&p_aggl, g_aggl);
    cudaGetSymbolAddress((void**)&p_xh, g_xh);
    cudaGetSymbolAddress((void**)&p_xl, g_xl);
    cudaGetSymbolAddress((void**)&p_Wih_h, g_Wih_h);
    cudaGetSymbolAddress((void**)&p_Wih_l, g_Wih_l);
    cudaGetSymbolAddress((void**)&p_Wcat_h, g_Wcat_h);
    cudaGetSymbolAddress((void**)&p_Wcat_l, g_Wcat_l);
    cudaGetSymbolAddress((void**)&p_cbias, g_cbias);

    cudaFuncSetAttribute(hmma_gemm<0, true, false>,
                         cudaFuncAttributeMaxDynamicSharedMemorySize, HG_SMEM);
    cudaFuncSetAttribute(hmma_gemm<2, false, false>,
                         cudaFuncAttributeMaxDynamicSharedMemorySize, HG_SMEM);
    cudaFuncSetAttribute(hmma_gemm<3, true, false>,
                         cudaFuncAttributeMaxDynamicSharedMemorySize, HG_SMEM);

    // ---- one-time prep ----
    adj_split<<<(int)(((size_t)DB * Nn * Nn / 4 + 255) / 256), 256>>>(
        (const float4*)adj);
    split_elem<<<(Ll * TO * Oo + 255) / 256, 256>>>(Wih, p_Wih_h, p_Wih_l,
                                                    Ll * TO * Oo);
    split_elem<<<(Nn * Bb * Ff + 255) / 256, 256>>>(inputs, p_xh, p_xl,
                                                    Nn * Bb * Ff);
    concat_w<<<(Ll * NCAT * Ff + 255) / 256, 256>>>(W, Whh, Wh, Bc, bhh, Bh);

    for (int l = 0; l < Ll; l++) {
        const float* xin = (l == 0) ? inputs : p_x;
        float* xout = (l == Ll - 1) ? (float*)d_out : p_x;

        // combined: support (scatter) | gh | t(relu) = x @ Wcat + cbias
        hmma_gemm<3, true, false><<<dim3(NCAT / 128, (Nn * Bb) / 128, 1), 256,
                                    HG_SMEM>>>(
            p_xh, p_xl, 0,
            p_Wcat_h + (size_t)l * NCAT * Ff, p_Wcat_l + (size_t)l * NCAT * Ff,
            0, p_cbias + l * NCAT, 0, p_sup, 0, nullptr, nullptr, p_gh, p_t,
            NCAT, Ff);

        // supT hi/lo bf16 [db][o][n]
        sup_splitT<<<dim3(Nn / 32, Oo / 32, DB), dim3(32, 8)>>>(p_sup);

        // agg[db] = adj[db] @ supT[db]^T   -> bf16 hi/lo out (feeds gi)
        hmma_gemm<2, false, false><<<dim3(1, Nn / 128, DB), 256, HG_SMEM>>>(
            p_adjh, p_adjl, (size_t)Nn * Nn, p_supTh, p_supTl, (size_t)Oo * Nn,
            nullptr, 0, nullptr, (size_t)Nn * Oo, p_aggh, p_aggl, nullptr,
            nullptr, Oo, Nn);

        // gi = agg @ Wih^T + bih
        hmma_gemm<0, true, false><<<dim3(TO / 128, (DB * Nn) / 128, 1), 256,
                                    HG_SMEM>>>(
            p_aggh, p_aggl, 0,
            p_Wih_h + (size_t)l * TO * Oo, p_Wih_l + (size_t)l * TO * Oo, 0,
            bih + (size_t)l * TO, 0, p_gi, 0, nullptr, nullptr, nullptr,
            nullptr, TO, Oo);

        // fused GRU + sum_d + relu + highway (+ emit next layer's x splits)
        gru_highway<<<(Nn * Bb * Oo) / 256, 256>>>(
            xin, p_gi, p_gh, p_t, xout, p_xh, p_xl, (l < Ll - 1) ? 1 : 0);
    }
}